// round 3
// baseline (speedup 1.0000x reference)
#include <cuda_runtime.h>
#include <cstddef>

// Problem constants (fixed by the dataset).
#define Bn 64
#define Pn 512
#define Qn 64
#define Dn 512
#define H4n 1024
#define G3n 1536
#define NT 256  // threads per CTA everywhere

// ---------------- scratch (device globals; no allocations allowed) ----------
__device__ float g_aT[Qn * Bn * Dn];   // (Q,B,D)  question @ Wuq^T, rows m=q*64+b
__device__ float g_bT[Pn * Bn * Dn];   // (P,B,D)  passage @ Wup^T, rows p*64+b
__device__ float g_h[2][Bn * Dn];      // GRU hidden, ping-pong
__device__ float g_c[Bn * Dn];         // h @ Wvp^T
__device__ float g_S[Qn * Bn * Dn];    // tanh(aT+b+c) @ Wv^T, rows m=q*64+b
__device__ float g_ct[Bn * Dn];        // attention context
__device__ float g_x[Bn * H4n];        // gated GRU input
__device__ float g_gi[Bn * G3n];       // x @ W_ih^T + b_ih
__device__ float g_gh[Bn * G3n];       // h @ W_hh^T + b_hh

// ---------------- software grid barrier -------------------------------------
__device__ unsigned g_cnt = 0;
__device__ volatile unsigned g_gen = 0;

__device__ __forceinline__ void grid_sync(int G) {
    __syncthreads();
    if (threadIdx.x == 0) {
        __threadfence();
        unsigned gen = g_gen;
        unsigned old = atomicAdd(&g_cnt, 1);
        if (old == (unsigned)(G - 1)) {
            atomicExch(&g_cnt, 0u);
            __threadfence();
            g_gen = gen + 1;
        } else {
            while (g_gen == gen) { __nanosleep(128); }
        }
        __threadfence();
    }
    __syncthreads();
}

// ---------------- precompute: 128x128x8 SGEMM NT with output-row permutation
// C[orow(m), n] = sum_k A[m,k]*Bw[n,k];  orow = (m%permInner)*(M/permInner)+m/permInner
__global__ void __launch_bounds__(NT) gemm128_nt(
    const float* __restrict__ A, const float* __restrict__ Bw,
    float* __restrict__ C, int M, int N, int K, int permInner)
{
    __shared__ float As[8][132];
    __shared__ float Bs[8][132];
    const int tid = threadIdx.x;
    const int bm = blockIdx.y, bn = blockIdx.x;
    const int lr = tid >> 1;
    const int lk = (tid & 1) * 4;
    const int tx = tid & 15, ty = tid >> 4;

    const float* Ab = A + (size_t)(bm * 128 + lr) * K + lk;
    const float* Bb = Bw + (size_t)(bn * 128 + lr) * K + lk;

    float acc[8][8];
#pragma unroll
    for (int i = 0; i < 8; i++)
#pragma unroll
        for (int j = 0; j < 8; j++) acc[i][j] = 0.0f;

    for (int k0 = 0; k0 < K; k0 += 8) {
        float4 av = *(const float4*)(Ab + k0);
        float4 bv = *(const float4*)(Bb + k0);
        __syncthreads();
        As[lk + 0][lr] = av.x; As[lk + 1][lr] = av.y;
        As[lk + 2][lr] = av.z; As[lk + 3][lr] = av.w;
        Bs[lk + 0][lr] = bv.x; Bs[lk + 1][lr] = bv.y;
        Bs[lk + 2][lr] = bv.z; Bs[lk + 3][lr] = bv.w;
        __syncthreads();
#pragma unroll
        for (int kk = 0; kk < 8; kk++) {
            float a[8], b[8];
            *(float4*)&a[0] = *(const float4*)&As[kk][ty * 4];
            *(float4*)&a[4] = *(const float4*)&As[kk][ty * 4 + 64];
            *(float4*)&b[0] = *(const float4*)&Bs[kk][tx * 4];
            *(float4*)&b[4] = *(const float4*)&Bs[kk][tx * 4 + 64];
#pragma unroll
            for (int i = 0; i < 8; i++)
#pragma unroll
                for (int j = 0; j < 8; j++)
                    acc[i][j] = fmaf(a[i], b[j], acc[i][j]);
        }
    }

    const int outer = M / permInner;
#pragma unroll
    for (int i = 0; i < 8; i++) {
        int rl = ty * 4 + ((i < 4) ? i : (60 + i));
        int m = bm * 128 + rl;
        int orow = (m % permInner) * outer + m / permInner;
        float* Crow = C + (size_t)orow * N + bn * 128;
        *(float4*)&Crow[tx * 4] =
            make_float4(acc[i][0], acc[i][1], acc[i][2], acc[i][3]);
        *(float4*)&Crow[tx * 4 + 64] =
            make_float4(acc[i][4], acc[i][5], acc[i][6], acc[i][7]);
    }
}

// ---------------- in-kernel tiles -------------------------------------------

// S tile: 128x128 of S = tanh(aT + bT[p] + c) @ Wv^T  (tanh fused on A load)
__device__ void s_tile(int bm, int bn, int p, const float* __restrict__ Wv,
                       float* sh, int tid)
{
    float (*As)[132] = (float(*)[132])sh;
    float (*Bs)[132] = (float(*)[132])(sh + 8 * 132);
    const int lr = tid >> 1;
    const int lk = (tid & 1) * 4;
    const int tx = tid & 15, ty = tid >> 4;

    const int m = bm * 128 + lr;     // S row = q*64+b
    const int b = m & 63;
    const float* aRow  = g_aT + (size_t)m * Dn + lk;
    const float* btRow = g_bT + ((size_t)p * Bn + b) * Dn + lk;
    const float* cRow  = g_c + (size_t)b * Dn + lk;
    const float* wRow  = Wv + (size_t)(bn * 128 + lr) * Dn + lk;

    float acc[8][8];
#pragma unroll
    for (int i = 0; i < 8; i++)
#pragma unroll
        for (int j = 0; j < 8; j++) acc[i][j] = 0.0f;

    for (int k0 = 0; k0 < Dn; k0 += 8) {
        float4 a4 = *(const float4*)(aRow + k0);
        float4 b4 = *(const float4*)(btRow + k0);
        float4 c4 = *(const float4*)(cRow + k0);
        float4 w4 = *(const float4*)(wRow + k0);
        float t0 = tanhf(a4.x + b4.x + c4.x);
        float t1 = tanhf(a4.y + b4.y + c4.y);
        float t2 = tanhf(a4.z + b4.z + c4.z);
        float t3 = tanhf(a4.w + b4.w + c4.w);
        __syncthreads();
        As[lk + 0][lr] = t0; As[lk + 1][lr] = t1;
        As[lk + 2][lr] = t2; As[lk + 3][lr] = t3;
        Bs[lk + 0][lr] = w4.x; Bs[lk + 1][lr] = w4.y;
        Bs[lk + 2][lr] = w4.z; Bs[lk + 3][lr] = w4.w;
        __syncthreads();
#pragma unroll
        for (int kk = 0; kk < 8; kk++) {
            float a[8], bb[8];
            *(float4*)&a[0]  = *(const float4*)&As[kk][ty * 4];
            *(float4*)&a[4]  = *(const float4*)&As[kk][ty * 4 + 64];
            *(float4*)&bb[0] = *(const float4*)&Bs[kk][tx * 4];
            *(float4*)&bb[4] = *(const float4*)&Bs[kk][tx * 4 + 64];
#pragma unroll
            for (int i = 0; i < 8; i++)
#pragma unroll
                for (int j = 0; j < 8; j++)
                    acc[i][j] = fmaf(a[i], bb[j], acc[i][j]);
        }
    }

#pragma unroll
    for (int i = 0; i < 8; i++) {
        int rl = ty * 4 + ((i < 4) ? i : (60 + i));
        int row = bm * 128 + rl;
        float* Crow = g_S + (size_t)row * Dn + bn * 128;
        *(float4*)&Crow[tx * 4] =
            make_float4(acc[i][0], acc[i][1], acc[i][2], acc[i][3]);
        *(float4*)&Crow[tx * 4 + 64] =
            make_float4(acc[i][4], acc[i][5], acc[i][6], acc[i][7]);
    }
}

// small-M GEMM tile: 64 rows x 16 cols, NT.
// MODE 0: c = h@Wvp^T           MODE 1: x = sigmoid(pa@Wg^T)*pa  (pa=[passage_p, ct])
// MODE 2: gi = x@W_ih^T + b_ih  MODE 3: gh = h@W_hh^T + b_hh
template <int MODE>
__device__ void gemm64_tile(const float* __restrict__ A, const float* __restrict__ A2,
                            const float* __restrict__ W, const float* __restrict__ bias,
                            float* __restrict__ Cout, int N, int K, int strideA,
                            int n0, float* sh, int tid)
{
    float (*As)[68] = (float(*)[68])sh;             // [32][68]
    float (*Ws)[17] = (float(*)[17])(sh + 32 * 68); // [32][17]
    const int ar = tid >> 2, ak = (tid & 3) * 8;
    const int wr = tid >> 4, wk = (tid & 15) * 2;
    const int m0 = (tid & 15) * 4, n = tid >> 4;

    float acc[4] = {0.f, 0.f, 0.f, 0.f};

    for (int k0 = 0; k0 < K; k0 += 32) {
        float av[8];
        if (MODE == 1) {
#pragma unroll
            for (int j = 0; j < 8; j++) {
                int k = k0 + ak + j;
                av[j] = (k < 512) ? A[(size_t)ar * strideA + k]
                                  : A2[ar * 512 + (k - 512)];
            }
        } else {
            float4 v0 = *(const float4*)&A[(size_t)ar * K + k0 + ak];
            float4 v1 = *(const float4*)&A[(size_t)ar * K + k0 + ak + 4];
            av[0] = v0.x; av[1] = v0.y; av[2] = v0.z; av[3] = v0.w;
            av[4] = v1.x; av[5] = v1.y; av[6] = v1.z; av[7] = v1.w;
        }
        float wv0 = W[(size_t)(n0 + wr) * K + k0 + wk];
        float wv1 = W[(size_t)(n0 + wr) * K + k0 + wk + 1];
        __syncthreads();
#pragma unroll
        for (int j = 0; j < 8; j++) As[ak + j][ar] = av[j];
        Ws[wk][wr] = wv0;
        Ws[wk + 1][wr] = wv1;
        __syncthreads();
#pragma unroll
        for (int kk = 0; kk < 32; kk++) {
            float w = Ws[kk][n];
            float4 a = *(const float4*)&As[kk][m0];
            acc[0] = fmaf(a.x, w, acc[0]);
            acc[1] = fmaf(a.y, w, acc[1]);
            acc[2] = fmaf(a.z, w, acc[2]);
            acc[3] = fmaf(a.w, w, acc[3]);
        }
    }

    const int col = n0 + n;
#pragma unroll
    for (int i = 0; i < 4; i++) {
        int b = m0 + i;
        float v = acc[i];
        if (MODE == 1) {
            float pav = (col < 512) ? A[(size_t)b * strideA + col]
                                    : A2[b * 512 + (col - 512)];
            v = pav / (1.0f + __expf(-v));
        } else if (MODE == 2 || MODE == 3) {
            v += bias[col];
        }
        Cout[(size_t)b * N + col] = v;
    }
}

// softmax over batch dim + c_t accumulation: one job = 16 feature cols, all q.
__device__ void softmax_ct(int eb, const float* __restrict__ question,
                           float* sh, int tid)
{
    float (*red)[17] = (float(*)[17])sh;  // [16 groups][16 cols]
    const int te = tid & 15, tg = tid >> 4;   // tg handles b = tg*4 .. +3
    const int e = eb * 16 + te;

    float acc[4] = {0.f, 0.f, 0.f, 0.f};
    for (int q = 0; q < Qn; q++) {
        float sv[4];
#pragma unroll
        for (int i = 0; i < 4; i++)
            sv[i] = g_S[((size_t)(q * Bn) + tg * 4 + i) * Dn + e];
        float m = fmaxf(fmaxf(sv[0], sv[1]), fmaxf(sv[2], sv[3]));
        __syncthreads();
        red[tg][te] = m;
        __syncthreads();
        float gm = red[0][te];
#pragma unroll
        for (int g = 1; g < 16; g++) gm = fmaxf(gm, red[g][te]);
        float s = 0.f;
#pragma unroll
        for (int i = 0; i < 4; i++) { sv[i] = __expf(sv[i] - gm); s += sv[i]; }
        __syncthreads();
        red[tg][te] = s;
        __syncthreads();
        float gs = red[0][te];
#pragma unroll
        for (int g = 1; g < 16; g++) gs += red[g][te];
        float inv = 1.0f / gs;
#pragma unroll
        for (int i = 0; i < 4; i++) {
            int b = tg * 4 + i;
            acc[i] += sv[i] * inv * question[((size_t)b * Qn + q) * Dn + e];
        }
    }
#pragma unroll
    for (int i = 0; i < 4; i++)
        g_ct[(tg * 4 + i) * Dn + e] = acc[i];
}

// ---------------- the persistent scan kernel --------------------------------
__global__ void __launch_bounds__(NT) fused_scan(
    const float* __restrict__ passage, const float* __restrict__ question,
    const float* __restrict__ Wvp, const float* __restrict__ Wv,
    const float* __restrict__ Wg, const float* __restrict__ W_ih,
    const float* __restrict__ W_hh, const float* __restrict__ b_ih,
    const float* __restrict__ b_hh, float* __restrict__ out, int G)
{
    __shared__ float sh[2736];
    const int bid = blockIdx.x, tid = threadIdx.x;

    // init h = 0
    for (int i = bid * NT + tid; i < Bn * Dn; i += G * NT) g_h[0][i] = 0.0f;
    grid_sync(G);

    for (int p = 0; p < Pn; p++) {
        const int cur = p & 1;
        const float* hcur = g_h[cur];

        // Phase A: c = h@Wvp^T (32 jobs) and gh = h@W_hh^T + b_hh (96 jobs)
        for (int job = bid; job < 128; job += G) {
            if (job < 32)
                gemm64_tile<0>(hcur, nullptr, Wvp, nullptr, g_c,
                               Dn, Dn, 0, job * 16, sh, tid);
            else
                gemm64_tile<3>(hcur, nullptr, W_hh, b_hh, g_gh,
                               G3n, Dn, 0, (job - 32) * 16, sh, tid);
        }
        grid_sync(G);

        // Phase B: S = tanh(aT + bT[p] + c) @ Wv^T  (128 tiles)
        for (int job = bid; job < 128; job += G)
            s_tile(job >> 2, job & 3, p, Wv, sh, tid);
        grid_sync(G);

        // Phase C: softmax over batch + c_t (32 jobs)
        for (int job = bid; job < 32; job += G)
            softmax_ct(job, question, sh, tid);
        grid_sync(G);

        // Phase D: x = sigmoid(pa@Wg^T)*pa (64 jobs)
        for (int job = bid; job < 64; job += G)
            gemm64_tile<1>(passage + (size_t)p * Dn, g_ct, Wg, nullptr, g_x,
                           H4n, H4n, Pn * Dn, job * 16, sh, tid);
        grid_sync(G);

        // Phase E: gi = x@W_ih^T + b_ih (96 jobs)
        for (int job = bid; job < 96; job += G)
            gemm64_tile<2>(g_x, nullptr, W_ih, b_ih, g_gi,
                           G3n, H4n, 0, job * 16, sh, tid);
        grid_sync(G);

        // Phase F: GRU elementwise update + output write
        for (int i = bid * NT + tid; i < Bn * Dn; i += G * NT) {
            int b = i >> 9, d = i & 511;
            const float* gi = &g_gi[b * G3n];
            const float* gh = &g_gh[b * G3n];
            float r = 1.0f / (1.0f + __expf(-(gi[d] + gh[d])));
            float z = 1.0f / (1.0f + __expf(-(gi[512 + d] + gh[512 + d])));
            float nn = tanhf(gi[1024 + d] + r * gh[1024 + d]);
            float h = hcur[i];
            float hnew = (1.0f - z) * nn + z * h;
            g_h[cur ^ 1][i] = hnew;
            out[((size_t)b * Pn + p) * Dn + d] = hnew;
        }
        grid_sync(G);
    }
}

// ---------------- launch -----------------------------------------------------
extern "C" void kernel_launch(void* const* d_in, const int* in_sizes, int n_in,
                              void* d_out, int out_size) {
    (void)in_sizes; (void)n_in; (void)out_size;
    const float* passage  = (const float*)d_in[0];
    const float* question = (const float*)d_in[1];
    const float* Wuq  = (const float*)d_in[2];
    const float* Wup  = (const float*)d_in[3];
    const float* Wvp  = (const float*)d_in[4];
    const float* Wv   = (const float*)d_in[5];
    const float* Wg   = (const float*)d_in[6];
    const float* W_ih = (const float*)d_in[7];
    const float* W_hh = (const float*)d_in[8];
    const float* b_ih = (const float*)d_in[9];
    const float* b_hh = (const float*)d_in[10];
    float* out = (float*)d_out;

    void *p_aT, *p_bT;
    cudaGetSymbolAddress(&p_aT, g_aT);
    cudaGetSymbolAddress(&p_bT, g_bT);
    float* aT = (float*)p_aT;
    float* bT = (float*)p_bT;

    // Grid size: clamp to guaranteed co-residency so grid_sync can never
    // deadlock (1 CTA/SM expected; occupancy query makes it explicit).
    int sms = 0;
    cudaDeviceGetAttribute(&sms, cudaDevAttrMultiProcessorCount, 0);
    if (sms <= 0) sms = 148;
    int perSM = 0;
    cudaOccupancyMaxActiveBlocksPerMultiprocessor(&perSM, fused_scan, NT, 2736 * 4);
    if (perSM < 1) perSM = 1;
    int G = sms * perSM;
    if (G > 512) G = 512;  // more CTAs than jobs in the widest phase is useless

    // Precompute aT (rows q*64+b) and bT (rows p*64+b).
    gemm128_nt<<<dim3(4, 32),  NT>>>(question, Wuq, aT, Bn * Qn, Dn, Dn, Qn);
    gemm128_nt<<<dim3(4, 256), NT>>>(passage,  Wup, bT, Bn * Pn, Dn, Dn, Pn);

    // The whole 512-step scan in one persistent kernel (3 graph nodes total).
    fused_scan<<<G, NT>>>(passage, question, Wvp, Wv, Wg, W_ih, W_hh,
                          b_ih, b_hh, out, G);
}

// round 5
// speedup vs baseline: 1.4397x; 1.4397x over previous
#include <cuda_runtime.h>
#include <cuda_bf16.h>
#include <cstdint>
#include <cstddef>

// Problem constants (fixed by the dataset).
#define Bn 64
#define Pn 512
#define Qn 64
#define Dn 512
#define H4n 1024
#define G3n 1536
#define NT 256

// ---------------- scratch (device globals; no allocations allowed) ----------
__device__ float g_aT[Qn * Bn * Dn];   // rows m=q*64+b
__device__ float g_bT[Pn * Bn * Dn];   // rows p*64+b
__device__ float g_h[2][Bn * Dn];
__device__ float g_c[Bn * Dn];
__device__ float g_S[Qn * Bn * Dn];    // rows m=q*64+b, cols e
__device__ float g_ct[Bn * Dn];
__device__ float g_x[Bn * H4n];
__device__ float g_gi[Bn * G3n];
__device__ float g_gh[Bn * G3n];
// Wv split into bf16 hi/lo, plain row-major [n][k]
__device__ __nv_bfloat16 g_WvH[Dn * Dn];
__device__ __nv_bfloat16 g_WvL[Dn * Dn];

// ---------------- software grid barrier -------------------------------------
__device__ unsigned g_cnt = 0;
__device__ volatile unsigned g_gen = 0;

__device__ __forceinline__ void grid_sync(int G) {
    __syncthreads();
    if (threadIdx.x == 0) {
        __threadfence();
        unsigned gen = g_gen;
        unsigned old = atomicAdd(&g_cnt, 1);
        if (old == (unsigned)(G - 1)) {
            atomicExch(&g_cnt, 0u);
            __threadfence();
            g_gen = gen + 1;
        } else {
            while (g_gen == gen) { }
        }
        __threadfence();
    }
    __syncthreads();
}

// ---------------- PTX helpers ------------------------------------------------
__device__ __forceinline__ uint32_t s2u(const void* p) {
    uint32_t r;
    asm("{ .reg .u64 t; cvta.to.shared.u64 t, %1; cvt.u32.u64 %0, t; }"
        : "=r"(r) : "l"(p));
    return r;
}

__device__ __forceinline__ void ldsm4(uint32_t* r, uint32_t addr) {
    asm volatile("ldmatrix.sync.aligned.m8n8.x4.shared.b16 {%0,%1,%2,%3}, [%4];"
                 : "=r"(r[0]), "=r"(r[1]), "=r"(r[2]), "=r"(r[3]) : "r"(addr));
}

__device__ __forceinline__ void mma16816(float* d, const uint32_t* a,
                                         const uint32_t* b) {
    asm volatile(
        "mma.sync.aligned.m16n8k16.row.col.f32.bf16.bf16.f32 "
        "{%0,%1,%2,%3}, {%4,%5,%6,%7}, {%8,%9}, {%0,%1,%2,%3};"
        : "+f"(d[0]), "+f"(d[1]), "+f"(d[2]), "+f"(d[3])
        : "r"(a[0]), "r"(a[1]), "r"(a[2]), "r"(a[3]), "r"(b[0]), "r"(b[1]));
}

__device__ __forceinline__ float fast_tanh(float x) {
    float t = __expf(2.0f * x);
    return 1.0f - __fdividef(2.0f, t + 1.0f);
}

// ---------------- precompute: 128x128x8 SGEMM NT with output-row permutation
__global__ void __launch_bounds__(NT) gemm128_nt(
    const float* __restrict__ A, const float* __restrict__ Bw,
    float* __restrict__ C, int M, int N, int K, int permInner)
{
    __shared__ float As[8][132];
    __shared__ float Bs[8][132];
    const int tid = threadIdx.x;
    const int bm = blockIdx.y, bn = blockIdx.x;
    const int lr = tid >> 1;
    const int lk = (tid & 1) * 4;
    const int tx = tid & 15, ty = tid >> 4;

    const float* Ab = A + (size_t)(bm * 128 + lr) * K + lk;
    const float* Bb = Bw + (size_t)(bn * 128 + lr) * K + lk;

    float acc[8][8];
#pragma unroll
    for (int i = 0; i < 8; i++)
#pragma unroll
        for (int j = 0; j < 8; j++) acc[i][j] = 0.0f;

    for (int k0 = 0; k0 < K; k0 += 8) {
        float4 av = *(const float4*)(Ab + k0);
        float4 bv = *(const float4*)(Bb + k0);
        __syncthreads();
        As[lk + 0][lr] = av.x; As[lk + 1][lr] = av.y;
        As[lk + 2][lr] = av.z; As[lk + 3][lr] = av.w;
        Bs[lk + 0][lr] = bv.x; Bs[lk + 1][lr] = bv.y;
        Bs[lk + 2][lr] = bv.z; Bs[lk + 3][lr] = bv.w;
        __syncthreads();
#pragma unroll
        for (int kk = 0; kk < 8; kk++) {
            float a[8], b[8];
            *(float4*)&a[0] = *(const float4*)&As[kk][ty * 4];
            *(float4*)&a[4] = *(const float4*)&As[kk][ty * 4 + 64];
            *(float4*)&b[0] = *(const float4*)&Bs[kk][tx * 4];
            *(float4*)&b[4] = *(const float4*)&Bs[kk][tx * 4 + 64];
#pragma unroll
            for (int i = 0; i < 8; i++)
#pragma unroll
                for (int j = 0; j < 8; j++)
                    acc[i][j] = fmaf(a[i], b[j], acc[i][j]);
        }
    }

    const int outer = M / permInner;
#pragma unroll
    for (int i = 0; i < 8; i++) {
        int rl = ty * 4 + ((i < 4) ? i : (60 + i));
        int m = bm * 128 + rl;
        int orow = (m % permInner) * outer + m / permInner;
        float* Crow = C + (size_t)orow * N + bn * 128;
        *(float4*)&Crow[tx * 4] =
            make_float4(acc[i][0], acc[i][1], acc[i][2], acc[i][3]);
        *(float4*)&Crow[tx * 4 + 64] =
            make_float4(acc[i][4], acc[i][5], acc[i][6], acc[i][7]);
    }
}

// ---------------- precompute: split Wv into bf16 hi/lo (row-major) ----------
__global__ void __launch_bounds__(NT) split_wv(const float* __restrict__ Wv) {
    int idx = blockIdx.x * NT + threadIdx.x;   // 512*512
    float v = Wv[idx];
    __nv_bfloat16 hi = __float2bfloat16(v);
    __nv_bfloat16 lo = __float2bfloat16(v - __bfloat162float(hi));
    g_WvH[idx] = hi;
    g_WvL[idx] = lo;
}

// ---------------- small-M GEMM tile (fp32 SIMT) ------------------------------
template <int MODE>
__device__ void gemm64_tile(const float* __restrict__ A, const float* __restrict__ A2,
                            const float* __restrict__ W, const float* __restrict__ bias,
                            float* __restrict__ Cout, int N, int K, int strideA,
                            int n0, float* sh, int tid)
{
    float (*As)[68] = (float(*)[68])sh;
    float (*Ws)[17] = (float(*)[17])(sh + 32 * 68);
    const int ar = tid >> 2, ak = (tid & 3) * 8;
    const int wr = tid >> 4, wk = (tid & 15) * 2;
    const int m0 = (tid & 15) * 4, n = tid >> 4;

    float acc[4] = {0.f, 0.f, 0.f, 0.f};

    for (int k0 = 0; k0 < K; k0 += 32) {
        float av[8];
        if (MODE == 1) {
#pragma unroll
            for (int j = 0; j < 8; j++) {
                int k = k0 + ak + j;
                av[j] = (k < 512) ? A[(size_t)ar * strideA + k]
                                  : A2[ar * 512 + (k - 512)];
            }
        } else {
            float4 v0 = *(const float4*)&A[(size_t)ar * K + k0 + ak];
            float4 v1 = *(const float4*)&A[(size_t)ar * K + k0 + ak + 4];
            av[0] = v0.x; av[1] = v0.y; av[2] = v0.z; av[3] = v0.w;
            av[4] = v1.x; av[5] = v1.y; av[6] = v1.z; av[7] = v1.w;
        }
        float wv0 = W[(size_t)(n0 + wr) * K + k0 + wk];
        float wv1 = W[(size_t)(n0 + wr) * K + k0 + wk + 1];
        __syncthreads();
#pragma unroll
        for (int j = 0; j < 8; j++) As[ak + j][ar] = av[j];
        Ws[wk][wr] = wv0;
        Ws[wk + 1][wr] = wv1;
        __syncthreads();
#pragma unroll
        for (int kk = 0; kk < 32; kk++) {
            float w = Ws[kk][n];
            float4 a = *(const float4*)&As[kk][m0];
            acc[0] = fmaf(a.x, w, acc[0]);
            acc[1] = fmaf(a.y, w, acc[1]);
            acc[2] = fmaf(a.z, w, acc[2]);
            acc[3] = fmaf(a.w, w, acc[3]);
        }
    }

    const int col = n0 + n;
#pragma unroll
    for (int i = 0; i < 4; i++) {
        int b = m0 + i;
        float v = acc[i];
        if (MODE == 1) {
            float pav = (col < 512) ? A[(size_t)b * strideA + col]
                                    : A2[b * 512 + (col - 512)];
            v = pav / (1.0f + __expf(-v));
        } else if (MODE == 2 || MODE == 3) {
            v += bias[col];
        }
        Cout[(size_t)b * N + col] = v;
    }
}

// ---------------- softmax over batch dim + c_t (R3 version) ------------------
__device__ void softmax_ct(int eb, const float* __restrict__ question,
                           float* sh, int tid)
{
    float (*red)[17] = (float(*)[17])sh;
    const int te = tid & 15, tg = tid >> 4;
    const int e = eb * 16 + te;

    float acc[4] = {0.f, 0.f, 0.f, 0.f};
    for (int q = 0; q < Qn; q++) {
        float sv[4];
#pragma unroll
        for (int i = 0; i < 4; i++)
            sv[i] = g_S[((size_t)(q * Bn) + tg * 4 + i) * Dn + e];
        float m = fmaxf(fmaxf(sv[0], sv[1]), fmaxf(sv[2], sv[3]));
        __syncthreads();
        red[tg][te] = m;
        __syncthreads();
        float gm = red[0][te];
#pragma unroll
        for (int g = 1; g < 16; g++) gm = fmaxf(gm, red[g][te]);
        float s = 0.f;
#pragma unroll
        for (int i = 0; i < 4; i++) { sv[i] = __expf(sv[i] - gm); s += sv[i]; }
        __syncthreads();
        red[tg][te] = s;
        __syncthreads();
        float gs = red[0][te];
#pragma unroll
        for (int g = 1; g < 16; g++) gs += red[g][te];
        float inv = 1.0f / gs;
#pragma unroll
        for (int i = 0; i < 4; i++) {
            int b = tg * 4 + i;
            acc[i] += sv[i] * inv * question[((size_t)b * Qn + q) * Dn + e];
        }
    }
#pragma unroll
    for (int i = 0; i < 4; i++)
        g_ct[(tg * 4 + i) * Dn + e] = acc[i];
}

// ---------------- phase-B tile: S = tanh(aT+bT[p]+c) @ Wv^T via mma.sync ----
// smem: Ah/Al/Bh/Bl, each [128][40] b16 (stride 40 = conflict-free ldmatrix)
#define BSTR 40
#define BUF_B (128 * BSTR * 2)  // bytes per buffer

__device__ void s_tile_mma(int tm, int tn, int p, unsigned char* dsm, int tid) {
    const uint32_t AhB = s2u(dsm);
    const uint32_t AlB = AhB + BUF_B;
    const uint32_t BhB = AlB + BUF_B;
    const uint32_t BlB = BhB + BUF_B;
    const int wid = tid >> 5, lane = tid & 31;
    const int wm = wid & 1, wn = wid >> 1;

    const int r = tid >> 1, hf = tid & 1;
    const int m = tm * 128 + r, bb = m & 63;
    const float* aP = g_aT + (size_t)m * Dn;
    const float* bP = g_bT + ((size_t)p * Bn + bb) * Dn;
    const float* cP = g_c + (size_t)bb * Dn;
    const __nv_bfloat16* wH = g_WvH + (size_t)(tn * 128 + r) * Dn;
    const __nv_bfloat16* wL = g_WvL + (size_t)(tn * 128 + r) * Dn;

    // smem write addresses (bytes): row r, 16 b16 at col hf*16
    const uint32_t wrOff = (uint32_t)(r * BSTR + hf * 16) * 2;

    // ldmatrix base offsets (bytes)
    const uint32_t aOff =
        (uint32_t)(((wm * 64 + (lane & 15)) * BSTR + (lane >> 4) * 8) * 2);
    const uint32_t bOff =
        (uint32_t)(((wn * 32 + ((lane >> 3) & 2) * 4 + (lane & 7)) * BSTR +
                    ((lane >> 3) & 1) * 8) * 2);

    float acc[4][4][4];
#pragma unroll
    for (int i = 0; i < 4; i++)
#pragma unroll
        for (int j = 0; j < 4; j++)
#pragma unroll
            for (int k = 0; k < 4; k++) acc[i][j][k] = 0.0f;

    for (int ch = 0; ch < 16; ch++) {
        const int k0 = ch * 32 + hf * 16;
        __syncthreads();
        // ---- A fill: tanh + hi/lo split, 16 elems/thread
        {
            uint32_t hw[8], lw[8];
#pragma unroll
            for (int i = 0; i < 4; i++) {
                float4 a4 = *(const float4*)(aP + k0 + i * 4);
                float4 b4 = *(const float4*)(bP + k0 + i * 4);
                float4 c4 = *(const float4*)(cP + k0 + i * 4);
                float t0 = fast_tanh(a4.x + b4.x + c4.x);
                float t1 = fast_tanh(a4.y + b4.y + c4.y);
                float t2 = fast_tanh(a4.z + b4.z + c4.z);
                float t3 = fast_tanh(a4.w + b4.w + c4.w);
                __nv_bfloat16 h0 = __float2bfloat16(t0);
                __nv_bfloat16 h1 = __float2bfloat16(t1);
                __nv_bfloat16 h2 = __float2bfloat16(t2);
                __nv_bfloat16 h3 = __float2bfloat16(t3);
                __nv_bfloat16 l0 = __float2bfloat16(t0 - __bfloat162float(h0));
                __nv_bfloat16 l1 = __float2bfloat16(t1 - __bfloat162float(h1));
                __nv_bfloat16 l2 = __float2bfloat16(t2 - __bfloat162float(h2));
                __nv_bfloat16 l3 = __float2bfloat16(t3 - __bfloat162float(h3));
                hw[i * 2]     = ((uint32_t)__bfloat16_as_ushort(h1) << 16) |
                                __bfloat16_as_ushort(h0);
                hw[i * 2 + 1] = ((uint32_t)__bfloat16_as_ushort(h3) << 16) |
                                __bfloat16_as_ushort(h2);
                lw[i * 2]     = ((uint32_t)__bfloat16_as_ushort(l1) << 16) |
                                __bfloat16_as_ushort(l0);
                lw[i * 2 + 1] = ((uint32_t)__bfloat16_as_ushort(l3) << 16) |
                                __bfloat16_as_ushort(l2);
            }
            asm volatile("st.shared.v4.b32 [%0], {%1,%2,%3,%4};" ::
                "r"(AhB + wrOff), "r"(hw[0]), "r"(hw[1]), "r"(hw[2]), "r"(hw[3]));
            asm volatile("st.shared.v4.b32 [%0], {%1,%2,%3,%4};" ::
                "r"(AhB + wrOff + 16), "r"(hw[4]), "r"(hw[5]), "r"(hw[6]), "r"(hw[7]));
            asm volatile("st.shared.v4.b32 [%0], {%1,%2,%3,%4};" ::
                "r"(AlB + wrOff), "r"(lw[0]), "r"(lw[1]), "r"(lw[2]), "r"(lw[3]));
            asm volatile("st.shared.v4.b32 [%0], {%1,%2,%3,%4};" ::
                "r"(AlB + wrOff + 16), "r"(lw[4]), "r"(lw[5]), "r"(lw[6]), "r"(lw[7]));
        }
        // ---- B fill: copy pre-split Wv rows
        {
            uint4 v0 = *(const uint4*)(wH + k0);
            uint4 v1 = *(const uint4*)(wH + k0 + 8);
            asm volatile("st.shared.v4.b32 [%0], {%1,%2,%3,%4};" ::
                "r"(BhB + wrOff), "r"(v0.x), "r"(v0.y), "r"(v0.z), "r"(v0.w));
            asm volatile("st.shared.v4.b32 [%0], {%1,%2,%3,%4};" ::
                "r"(BhB + wrOff + 16), "r"(v1.x), "r"(v1.y), "r"(v1.z), "r"(v1.w));
            uint4 u0 = *(const uint4*)(wL + k0);
            uint4 u1 = *(const uint4*)(wL + k0 + 8);
            asm volatile("st.shared.v4.b32 [%0], {%1,%2,%3,%4};" ::
                "r"(BlB + wrOff), "r"(u0.x), "r"(u0.y), "r"(u0.z), "r"(u0.w));
            asm volatile("st.shared.v4.b32 [%0], {%1,%2,%3,%4};" ::
                "r"(BlB + wrOff + 16), "r"(u1.x), "r"(u1.y), "r"(u1.z), "r"(u1.w));
        }
        __syncthreads();

        // ---- mma over 2 k16-steps
#pragma unroll
        for (int ks = 0; ks < 2; ks++) {
            uint32_t ah[4][4], al[4][4], bh[2][4], bl[2][4];
#pragma unroll
            for (int mi = 0; mi < 4; mi++) {
                ldsm4(ah[mi], AhB + aOff + mi * (16 * BSTR * 2) + ks * 32);
                ldsm4(al[mi], AlB + aOff + mi * (16 * BSTR * 2) + ks * 32);
            }
#pragma unroll
            for (int ng = 0; ng < 2; ng++) {
                ldsm4(bh[ng], BhB + bOff + ng * (16 * BSTR * 2) + ks * 32);
                ldsm4(bl[ng], BlB + bOff + ng * (16 * BSTR * 2) + ks * 32);
            }
#pragma unroll
            for (int mi = 0; mi < 4; mi++)
#pragma unroll
                for (int ni = 0; ni < 4; ni++) {
                    const int ng = ni >> 1, sub = ni & 1;
                    mma16816(acc[mi][ni], ah[mi], &bh[ng][sub * 2]);
                    mma16816(acc[mi][ni], ah[mi], &bl[ng][sub * 2]);
                    mma16816(acc[mi][ni], al[mi], &bh[ng][sub * 2]);
                }
        }
    }

    // ---- store fragments to g_S
#pragma unroll
    for (int mi = 0; mi < 4; mi++) {
        const int row = tm * 128 + wm * 64 + mi * 16 + (lane >> 2);
#pragma unroll
        for (int ni = 0; ni < 4; ni++) {
            const int col = tn * 128 + wn * 32 + ni * 8 + (lane & 3) * 2;
            *(float2*)&g_S[(size_t)row * Dn + col] =
                make_float2(acc[mi][ni][0], acc[mi][ni][1]);
            *(float2*)&g_S[(size_t)(row + 8) * Dn + col] =
                make_float2(acc[mi][ni][2], acc[mi][ni][3]);
        }
    }
}

// ---------------- the persistent scan kernel --------------------------------
extern __shared__ unsigned char dsm[];

__global__ void __launch_bounds__(NT) fused_scan(
    const float* __restrict__ passage, const float* __restrict__ question,
    const float* __restrict__ Wvp, const float* __restrict__ Wg,
    const float* __restrict__ W_ih, const float* __restrict__ W_hh,
    const float* __restrict__ b_ih, const float* __restrict__ b_hh,
    float* __restrict__ out, int G)
{
    const int bid = blockIdx.x, tid = threadIdx.x;
    float* sh = (float*)dsm;

    // init h = 0
    for (int i = bid * NT + tid; i < Bn * Dn; i += G * NT) g_h[0][i] = 0.0f;
    grid_sync(G);

    for (int p = 0; p < Pn; p++) {
        const int cur = p & 1;
        const float* hcur = g_h[cur];

        // Phase A: c = h@Wvp^T (32 jobs), gh = h@W_hh^T + b_hh (96 jobs)
        for (int job = bid; job < 128; job += G) {
            if (job < 32)
                gemm64_tile<0>(hcur, nullptr, Wvp, nullptr, g_c,
                               Dn, Dn, 0, job * 16, sh, tid);
            else
                gemm64_tile<3>(hcur, nullptr, W_hh, b_hh, g_gh,
                               G3n, Dn, 0, (job - 32) * 16, sh, tid);
        }
        grid_sync(G);

        // Phase B: S = tanh(aT + bT[p] + c) @ Wv^T  (128 mma tiles)
        for (int job = bid; job < 128; job += G) {
            s_tile_mma(job >> 2, job & 3, p, dsm, tid);
            __syncthreads();
        }
        grid_sync(G);

        // Phase C: softmax over batch + c_t (32 jobs)
        for (int job = bid; job < 32; job += G)
            softmax_ct(job, question, sh, tid);
        grid_sync(G);

        // Phase D: x = sigmoid(pa@Wg^T)*pa (64 jobs)
        for (int job = bid; job < 64; job += G)
            gemm64_tile<1>(passage + (size_t)p * Dn, g_ct, Wg, nullptr, g_x,
                           H4n, H4n, Pn * Dn, job * 16, sh, tid);
        grid_sync(G);

        // Phase E: gi = x@W_ih^T + b_ih (96 jobs)
        for (int job = bid; job < 96; job += G)
            gemm64_tile<2>(g_x, nullptr, W_ih, b_ih, g_gi,
                           G3n, H4n, 0, job * 16, sh, tid);
        grid_sync(G);

        // Phase F: GRU elementwise update + output write
        for (int i = bid * NT + tid; i < Bn * Dn; i += G * NT) {
            int b = i >> 9, d = i & 511;
            const float* gi = &g_gi[b * G3n];
            const float* gh = &g_gh[b * G3n];
            float r = 1.0f / (1.0f + __expf(-(gi[d] + gh[d])));
            float z = 1.0f / (1.0f + __expf(-(gi[512 + d] + gh[512 + d])));
            float nn = tanhf(gi[1024 + d] + r * gh[1024 + d]);
            float h = hcur[i];
            float hnew = (1.0f - z) * nn + z * h;
            g_h[cur ^ 1][i] = hnew;
            out[((size_t)b * Pn + p) * Dn + d] = hnew;
        }
        grid_sync(G);
    }
}

// ---------------- launch -----------------------------------------------------
#define FS_SMEM (4 * BUF_B)   // 40960 bytes

extern "C" void kernel_launch(void* const* d_in, const int* in_sizes, int n_in,
                              void* d_out, int out_size) {
    (void)in_sizes; (void)n_in; (void)out_size;
    const float* passage  = (const float*)d_in[0];
    const float* question = (const float*)d_in[1];
    const float* Wuq  = (const float*)d_in[2];
    const float* Wup  = (const float*)d_in[3];
    const float* Wvp  = (const float*)d_in[4];
    const float* Wv   = (const float*)d_in[5];
    const float* Wg   = (const float*)d_in[6];
    const float* W_ih = (const float*)d_in[7];
    const float* W_hh = (const float*)d_in[8];
    const float* b_ih = (const float*)d_in[9];
    const float* b_hh = (const float*)d_in[10];
    float* out = (float*)d_out;

    void *p_aT, *p_bT;
    cudaGetSymbolAddress(&p_aT, g_aT);
    cudaGetSymbolAddress(&p_bT, g_bT);
    float* aT = (float*)p_aT;
    float* bT = (float*)p_bT;

    cudaFuncSetAttribute(fused_scan, cudaFuncAttributeMaxDynamicSharedMemorySize,
                         FS_SMEM);

    int G = 0;
    cudaDeviceGetAttribute(&G, cudaDevAttrMultiProcessorCount, 0);
    if (G <= 0) G = 148;

    // Precompute: aT rows q*64+b, bT rows p*64+b, Wv hi/lo split
    gemm128_nt<<<dim3(4, 32),  NT>>>(question, Wuq, aT, Bn * Qn, Dn, Dn, Qn);
    gemm128_nt<<<dim3(4, 256), NT>>>(passage,  Wup, bT, Bn * Pn, Dn, Dn, Pn);
    split_wv<<<(Dn * Dn) / NT, NT>>>(Wv);

    // The whole 512-step scan in one persistent kernel.
    fused_scan<<<G, NT, FS_SMEM>>>(passage, question, Wvp, Wg, W_ih, W_hh,
                                   b_ih, b_hh, out, G);
}